// round 17
// baseline (speedup 1.0000x reference)
#include <cuda_runtime.h>
#include <cuda_bf16.h>
#include <math.h>
#include <stdint.h>

// Problem dims (fixed)
#define NB 96
#define NQ 96
#define NV 197
#define NT 77
#define ND 768
#define NE 512

__device__ __nv_bfloat16 g_vtok[(size_t)NB * NV * NE];
__device__ __nv_bfloat16 g_ttok[(size_t)NQ * NT * NE];
// bf16 pre-converted GEMM inputs
__device__ __nv_bfloat16 g_xvb[(size_t)NB * NV * ND];
__device__ __nv_bfloat16 g_xtb[(size_t)NQ * NT * ND];
__device__ __nv_bfloat16 g_wvb[(size_t)NE * ND];
__device__ __nv_bfloat16 g_wtb[(size_t)NE * ND];

__device__ __forceinline__ uint32_t smem_u32(const void* p) {
    uint32_t a;
    asm("{ .reg .u64 t; cvta.to.shared.u64 t, %1; cvt.u32.u64 %0, t; }"
        : "=r"(a) : "l"(p));
    return a;
}
__device__ __forceinline__ void ldmatrix_x4(uint32_t* r, uint32_t addr) {
    asm volatile("ldmatrix.sync.aligned.m8n8.x4.shared.b16 {%0,%1,%2,%3}, [%4];"
        : "=r"(r[0]), "=r"(r[1]), "=r"(r[2]), "=r"(r[3]) : "r"(addr));
}
__device__ __forceinline__ void mma_16816(float* c, const uint32_t* a, const uint32_t* b) {
    asm volatile("mma.sync.aligned.m16n8k16.row.col.f32.bf16.bf16.f32 "
        "{%0,%1,%2,%3}, {%4,%5,%6,%7}, {%8,%9}, {%0,%1,%2,%3};"
        : "+f"(c[0]), "+f"(c[1]), "+f"(c[2]), "+f"(c[3])
        : "r"(a[0]), "r"(a[1]), "r"(a[2]), "r"(a[3]), "r"(b[0]), "r"(b[1]));
}
__device__ __forceinline__ void cp16(uint32_t dst, const void* src, bool pred) {
    int sz = pred ? 16 : 0;
    asm volatile("cp.async.cg.shared.global [%0], [%1], 16, %2;"
        :: "r"(dst), "l"(src), "r"(sz) : "memory");
}
#define CP_COMMIT() asm volatile("cp.async.commit_group;" ::: "memory")
__device__ __forceinline__ uint4 f32x8_bf16(float4 a, float4 b) {
    uint4 r;
    __nv_bfloat162 p;
    p = __float22bfloat162_rn(make_float2(a.x, a.y)); r.x = *(uint32_t*)&p;
    p = __float22bfloat162_rn(make_float2(a.z, a.w)); r.y = *(uint32_t*)&p;
    p = __float22bfloat162_rn(make_float2(b.x, b.y)); r.z = *(uint32_t*)&p;
    p = __float22bfloat162_rn(make_float2(b.z, b.w)); r.w = *(uint32_t*)&p;
    return r;
}

// ===========================================================================
// Convert fp32 inputs -> bf16 operand buffers
// ===========================================================================
#define CSEG0 ((size_t)NB * NV * ND)
#define CSEG1 (CSEG0 + (size_t)NQ * NT * ND)
#define CSEG2 (CSEG1 + (size_t)NE * ND)
#define CSEG3 (CSEG2 + (size_t)NE * ND)

__global__ __launch_bounds__(256) void convert_bf16(
    const float* __restrict__ xv, const float* __restrict__ xt,
    const float* __restrict__ wv, const float* __restrict__ wt)
{
    size_t e = ((size_t)blockIdx.x * 256 + threadIdx.x) * 8;
    if (e >= CSEG3) return;
    const float* src;
    __nv_bfloat16* dst;
    size_t off;
    if (e < CSEG0)      { src = xv; dst = g_xvb; off = e; }
    else if (e < CSEG1) { src = xt; dst = g_xtb; off = e - CSEG0; }
    else if (e < CSEG2) { src = wv; dst = g_wvb; off = e - CSEG1; }
    else                { src = wt; dst = g_wtb; off = e - CSEG2; }
    const float4* p = (const float4*)(src + off);
    *(uint4*)(dst + off) = f32x8_bf16(p[0], p[1]);
}

// ===========================================================================
// cls projections (exact fp32 SIMT), one launch via blockIdx.z
// ===========================================================================
__global__ __launch_bounds__(256) void proj_cls(
    const float* __restrict__ Xv, const float* __restrict__ Wv,
    const float* __restrict__ bv, float* __restrict__ Yv,
    const float* __restrict__ Xt, const float* __restrict__ Wt,
    const float* __restrict__ bt, float* __restrict__ Yt)
{
    const float* X = blockIdx.z ? Xt : Xv;
    const float* W = blockIdx.z ? Wt : Wv;
    const float* bias = blockIdx.z ? bt : bv;
    float* Y = blockIdx.z ? Yt : Yv;
    const int R = NB;

    __shared__ float As[16][68];
    __shared__ float Bs[16][68];
    const int r0 = blockIdx.x * 64, e0 = blockIdx.y * 64;
    const int tid = threadIdx.x;
    const int ty = tid >> 4, tx = tid & 15;
    const int lrow = tid >> 2, lk4 = tid & 3;

    float acc[4][4];
#pragma unroll
    for (int i = 0; i < 4; i++)
#pragma unroll
        for (int j = 0; j < 4; j++) acc[i][j] = 0.f;

    const int r_ld = r0 + lrow;
    const float4 zero4 = make_float4(0.f, 0.f, 0.f, 0.f);

    for (int k0 = 0; k0 < ND; k0 += 16) {
        float4 av = (r_ld < R)
            ? *(const float4*)(X + (size_t)r_ld * ND + k0 + lk4 * 4) : zero4;
        float4 bv4 = *(const float4*)(W + (size_t)(e0 + lrow) * ND + k0 + lk4 * 4);
        __syncthreads();
        As[lk4 * 4 + 0][lrow] = av.x; As[lk4 * 4 + 1][lrow] = av.y;
        As[lk4 * 4 + 2][lrow] = av.z; As[lk4 * 4 + 3][lrow] = av.w;
        Bs[lk4 * 4 + 0][lrow] = bv4.x; Bs[lk4 * 4 + 1][lrow] = bv4.y;
        Bs[lk4 * 4 + 2][lrow] = bv4.z; Bs[lk4 * 4 + 3][lrow] = bv4.w;
        __syncthreads();
#pragma unroll
        for (int kk = 0; kk < 16; kk++) {
            float4 a = *(const float4*)&As[kk][ty * 4];
            float4 b = *(const float4*)&Bs[kk][tx * 4];
            float aa[4] = {a.x, a.y, a.z, a.w};
            float bb[4] = {b.x, b.y, b.z, b.w};
#pragma unroll
            for (int i = 0; i < 4; i++)
#pragma unroll
                for (int j = 0; j < 4; j++)
                    acc[i][j] = fmaf(aa[i], bb[j], acc[i][j]);
        }
    }
#pragma unroll
    for (int i = 0; i < 4; i++) {
        int r = r0 + ty * 4 + i;
        if (r < R) {
#pragma unroll
            for (int j = 0; j < 4; j++) {
                int e = e0 + tx * 4 + j;
                Y[(size_t)r * NE + e] = acc[i][j] + bias[e];
            }
        }
    }
}

// ===========================================================================
// Token projection v4: one sync per chunk; writes bf16 DIRECTLY to g_vtok/g_ttok
// ===========================================================================
#define PPITCH 144
#define PBOFF  (128 * PPITCH)
#define PSTAGE (2 * PBOFF)
#define VIS_BX 148
#define TEX_BX 58

__global__ __launch_bounds__(256, 2) void proj_mma2(
    const float* __restrict__ bias_v, const float* __restrict__ bias_t)
{
    const int z = blockIdx.z;
    if (z == 1 && blockIdx.x >= TEX_BX) return;
    const int R = z ? (NQ * NT) : (NB * NV);
    const uint4* Xb = (const uint4*)(z ? g_xtb : g_xvb);
    const uint4* Wb = (const uint4*)(z ? g_wtb : g_wvb);
    const float* bias = z ? bias_t : bias_v;
    __nv_bfloat16* Y = z ? g_ttok : g_vtok;

    extern __shared__ __align__(16) char psm[];
    const uint32_t st0 = smem_u32(psm), st1 = st0 + PSTAGE;

    const int tid = threadIdx.x, wid = tid >> 5, lane = tid & 31;
    const int r0 = blockIdx.x * 128, e0 = blockIdx.y * 128;
    const int mrow = (wid & 3) * 32, ncol = (wid >> 2) * 64;

    const uint32_t aoff = (uint32_t)(mrow + (lane & 7) + ((lane >> 3) & 1) * 8) * PPITCH
                        + (uint32_t)(lane >> 4) * 16;
    const uint32_t boff = PBOFF
                        + (uint32_t)(ncol + (lane & 7) + ((lane >> 4) << 3)) * PPITCH
                        + (uint32_t)((lane >> 3) & 1) * 16;

    float c[2][8][4];
#pragma unroll
    for (int mi = 0; mi < 2; mi++)
#pragma unroll
        for (int ni = 0; ni < 8; ni++)
#pragma unroll
            for (int j = 0; j < 4; j++) c[mi][ni][j] = 0.f;

    auto issue = [&](int ch, uint32_t sbase) {
        const int k4 = ch * 8;
#pragma unroll
        for (int it = 0; it < 8; it++) {
            int slot = it * 256 + tid, row = slot >> 3, seg = slot & 7;
            if (row < 128) {
                bool ok = (r0 + row) < R;
                const uint4* src = Xb + (ok ? (size_t)(r0 + row) * 96 : 0) + k4 + seg;
                cp16(sbase + (uint32_t)(row * PPITCH + seg * 16), src, ok);
            } else {
                int wr = row - 128;
                const uint4* src = Wb + (size_t)(e0 + wr) * 96 + k4 + seg;
                cp16(sbase + (uint32_t)(PBOFF + wr * PPITCH + seg * 16), src, true);
            }
        }
    };

    issue(0, st0); CP_COMMIT();

    for (int ch = 0; ch < 12; ch++) {
        asm volatile("cp.async.wait_group 0;" ::: "memory");
        __syncthreads();

        const uint32_t sb = (ch & 1) ? st1 : st0;
        if (ch + 1 < 12) { issue(ch + 1, (ch & 1) ? st0 : st1); CP_COMMIT(); }

        const uint32_t aa = sb + aoff, ba = sb + boff;
#pragma unroll
        for (int ks = 0; ks < 4; ks++) {
            uint32_t af[2][4], bf[16];
#pragma unroll
            for (int mi = 0; mi < 2; mi++)
                ldmatrix_x4(af[mi], aa + mi * (16 * PPITCH) + ks * 32);
#pragma unroll
            for (int nn = 0; nn < 4; nn++)
                ldmatrix_x4(bf + nn * 4, ba + nn * (16 * PPITCH) + ks * 32);
#pragma unroll
            for (int mi = 0; mi < 2; mi++)
#pragma unroll
                for (int ni = 0; ni < 8; ni++)
                    mma_16816(c[mi][ni], af[mi], bf + ni * 2);
        }
    }

    // epilogue: add bias, write bf16 directly
#pragma unroll
    for (int mi = 0; mi < 2; mi++) {
        int rr = r0 + mrow + mi * 16 + (lane >> 2);
        if (rr < R) {
#pragma unroll
            for (int ni = 0; ni < 8; ni++) {
                int e = e0 + ncol + ni * 8 + ((lane & 3) << 1);
                float b0 = bias[e], b1 = bias[e + 1];
                __nv_bfloat162 o;
                o = __float22bfloat162_rn(make_float2(c[mi][ni][0] + b0,
                                                      c[mi][ni][1] + b1));
                *(__nv_bfloat162*)(Y + (size_t)rr * NE + e) = o;
                o = __float22bfloat162_rn(make_float2(c[mi][ni][2] + b0,
                                                      c[mi][ni][3] + b1));
                *(__nv_bfloat162*)(Y + (size_t)(rr + 8) * NE + e) = o;
            }
        }
    }
}

// ===========================================================================
// L2-normalize rows in place (bf16 in/out, fp32 accumulation)
// ===========================================================================
__global__ __launch_bounds__(256) void l2norm_rows()
{
    const int NROWS_V = NB * NV;
    const int NROWS = NROWS_V + NQ * NT;
    int row = blockIdx.x * 8 + (threadIdx.x >> 5);
    int lane = threadIdx.x & 31;
    if (row >= NROWS) return;
    __nv_bfloat16* p = (row < NROWS_V)
        ? (g_vtok + (size_t)row * NE)
        : (g_ttok + (size_t)(row - NROWS_V) * NE);
    __nv_bfloat162* p2 = (__nv_bfloat162*)p;
    float s = 0.f;
    float2 vals[8];
#pragma unroll
    for (int i = 0; i < 8; i++) {
        float2 v = __bfloat1622float2(p2[lane + i * 32]);
        vals[i] = v;
        s += v.x * v.x + v.y * v.y;
    }
#pragma unroll
    for (int off = 16; off > 0; off >>= 1)
        s += __shfl_xor_sync(0xffffffffu, s, off);
    float inv = 1.f / fmaxf(sqrtf(s), 1e-12f);
#pragma unroll
    for (int i = 0; i < 8; i++)
        p2[lane + i * 32] = __float22bfloat162_rn(
            make_float2(vals[i].x * inv, vals[i].y * inv));
}

// ===========================================================================
// Stage 2 v7: v6 + CTA-parity SMSP rotation of the m-tile map.
//   Per-CTA tile counts {4,3,3,3}/SMSP; parity rotation makes the two
//   co-resident CTAs bind different SMSPs -> SM combined {7,6,6,7} not {8,6,6,6}.
// ===========================================================================
#define APITCH 144
#define MROWS  208
#define BOFF2  (MROWS * APITCH)
#define STAGE  (BOFF2 + 80 * APITCH)
#define SMEM_DYN (2 * STAGE)
#define NINF   (-INFINITY)

__global__ __launch_bounds__(256, 2) void stage2(
    const int* __restrict__ text_length,
    float* __restrict__ t2v, float* __restrict__ v2t)
{
    extern __shared__ __align__(16) char dsm[];
    __shared__ float s_colmax[8][84];
    __shared__ float s_vsum[8];
    __shared__ float s_part[8];

    const int tid = threadIdx.x;
    const int wid = tid >> 5, lane = tid & 31;
    const int q = blockIdx.x, b = blockIdx.y;

    const int len = text_length[q];
    const int nnlim = (len + 15) >> 4;
    const int nrows = nnlim << 4;

    const uint4* Va = (const uint4*)(g_vtok + (size_t)b * NV * NE);
    const uint4* Tt = (const uint4*)(g_ttok + (size_t)q * NT * NE);

    const uint32_t st0 = smem_u32(dsm), st1 = st0 + STAGE;

    // parity-rotated m-tile assignment (warp-uniform)
    const int rot = (blockIdx.x + blockIdx.y) & 1;
    const int aw = (wid + rot) & 7;
    const int mcnt = (aw < 5) ? 2 : 1;
    const int moff = (aw < 5) ? aw * 32 : 160 + (aw - 5) * 16;
    const bool has2 = (mcnt == 2);

    const uint32_t aoff = (uint32_t)(moff + (lane & 7) + ((lane >> 3) & 1) * 8) * APITCH
                        + (uint32_t)(lane >> 4) * 16;
    const uint32_t boff = BOFF2
                        + (uint32_t)((lane & 7) + ((lane >> 4) << 3)) * APITCH
                        + (uint32_t)((lane >> 3) & 1) * 16;

    float c[2][10][4];
#pragma unroll
    for (int mi = 0; mi < 2; mi++)
#pragma unroll
        for (int ni = 0; ni < 10; ni++)
#pragma unroll
            for (int j = 0; j < 4; j++) c[mi][ni][j] = 0.f;

    // Weighted cp.async issue: light warps (tid >= 160) carry most of it.
    auto issue = [&](int ch, uint32_t sbase) {
        const int k4 = ch * 8;
        if (tid >= 160) {
            const int l = tid - 160;
#pragma unroll
            for (int it = 0; it < 12; it++) {
                int slot = it * 96 + l;
                int row = slot >> 3, seg = slot & 7;
                cp16(sbase + (uint32_t)(row * APITCH + seg * 16),
                     Va + row * 64 + k4 + seg, true);
            }
#pragma unroll
            for (int it = 0; it < 7; it++) {
                int slot = it * 96 + l;
                if (slot < 640) {
                    int row = slot >> 3, seg = slot & 7;
                    if (row < nrows) {
                        bool ok = row < NT;
                        const uint4* src = Tt + (ok ? row * 64 : 0) + k4 + seg;
                        cp16(sbase + (uint32_t)(BOFF2 + row * APITCH + seg * 16),
                             src, ok);
                    }
                }
            }
        } else {
#pragma unroll
            for (int it = 0; it < 3; it++) {
                int slot = 1152 + it * 160 + tid;
                if (slot < NV * 8) {
                    int row = slot >> 3, seg = slot & 7;
                    cp16(sbase + (uint32_t)(row * APITCH + seg * 16),
                         Va + row * 64 + k4 + seg, true);
                }
            }
        }
    };

    issue(0, st0); CP_COMMIT();

    for (int ch = 0; ch < 8; ch++) {
        asm volatile("cp.async.wait_group 0;" ::: "memory");
        __syncthreads();

        const uint32_t sb = (ch & 1) ? st1 : st0;
        if (ch + 1 < 8) { issue(ch + 1, (ch & 1) ? st0 : st1); CP_COMMIT(); }

        const uint32_t aa = sb + aoff, ba = sb + boff;
#pragma unroll
        for (int ks = 0; ks < 4; ks++) {
            uint32_t af[2][4], bf[20];
            ldmatrix_x4(af[0], aa + ks * 32);
            if (has2) ldmatrix_x4(af[1], aa + 16 * APITCH + ks * 32);
#pragma unroll
            for (int nn = 0; nn < 5; nn++)
                if (nn < nnlim)
                    ldmatrix_x4(bf + nn * 4, ba + nn * (16 * APITCH) + ks * 32);
#pragma unroll
            for (int ni = 0; ni < 10; ni++)
                if (ni < 2 * nnlim)
                    mma_16816(c[0][ni], af[0], bf + ni * 2);
            if (has2) {
#pragma unroll
                for (int ni = 0; ni < 10; ni++)
                    if (ni < 2 * nnlim)
                        mma_16816(c[1][ni], af[1], bf + ni * 2);
            }
        }
    }

    // ---- register/shfl epilogue ----
    const int rb = moff + (lane >> 2);

    float rowmax[2][2] = {{NINF, NINF}, {NINF, NINF}};
    float colmax[10][2];
#pragma unroll
    for (int ni = 0; ni < 10; ni++) { colmax[ni][0] = NINF; colmax[ni][1] = NINF; }

#pragma unroll
    for (int mi = 0; mi < 2; mi++) {
        const bool active = (mi == 0) || has2;
        int r0 = rb + mi * 16;
        bool v0 = active && (r0 < NV), v8 = active && ((r0 + 8) < NV);
#pragma unroll
        for (int ni = 0; ni < 10; ni++) {
            int tl = ni * 8 + ((lane & 3) << 1);
            float* cf = c[mi][ni];
            float m0 = (tl     < len) ? cf[0] : ((tl     < NT) ? 0.f : NINF);
            float m1 = (tl + 1 < len) ? cf[1] : ((tl + 1 < NT) ? 0.f : NINF);
            float m2 = (tl     < len) ? cf[2] : ((tl     < NT) ? 0.f : NINF);
            float m3 = (tl + 1 < len) ? cf[3] : ((tl + 1 < NT) ? 0.f : NINF);
            rowmax[mi][0] = fmaxf(rowmax[mi][0], fmaxf(m0, m1));
            rowmax[mi][1] = fmaxf(rowmax[mi][1], fmaxf(m2, m3));
            colmax[ni][0] = fmaxf(colmax[ni][0],
                fmaxf(v0 ? cf[0] : NINF, v8 ? cf[2] : NINF));
            colmax[ni][1] = fmaxf(colmax[ni][1],
                fmaxf(v0 ? cf[1] : NINF, v8 ? cf[3] : NINF));
        }
    }

#pragma unroll
    for (int mi = 0; mi < 2; mi++)
#pragma unroll
        for (int h = 0; h < 2; h++) {
            float r = rowmax[mi][h];
            r = fmaxf(r, __shfl_xor_sync(0xffffffffu, r, 1));
            r = fmaxf(r, __shfl_xor_sync(0xffffffffu, r, 2));
            rowmax[mi][h] = r;
        }
    float rowsum = 0.f;
#pragma unroll
    for (int mi = 0; mi < 2; mi++) {
        const bool active = (mi == 0) || has2;
        int r0 = rb + mi * 16;
        if (active && r0 < NV)       rowsum += rowmax[mi][0];
        if (active && (r0 + 8) < NV) rowsum += rowmax[mi][1];
    }
    rowsum += __shfl_xor_sync(0xffffffffu, rowsum, 4);
    rowsum += __shfl_xor_sync(0xffffffffu, rowsum, 8);
    rowsum += __shfl_xor_sync(0xffffffffu, rowsum, 16);
    if (lane == 0) s_vsum[wid] = rowsum;

#pragma unroll
    for (int ni = 0; ni < 10; ni++)
#pragma unroll
        for (int h = 0; h < 2; h++) {
            float r = colmax[ni][h];
            r = fmaxf(r, __shfl_xor_sync(0xffffffffu, r, 4));
            r = fmaxf(r, __shfl_xor_sync(0xffffffffu, r, 8));
            r = fmaxf(r, __shfl_xor_sync(0xffffffffu, r, 16));
            colmax[ni][h] = r;
        }
    if (lane < 4) {
#pragma unroll
        for (int ni = 0; ni < 10; ni++) {
            int cc = ni * 8 + (lane << 1);
            s_colmax[wid][cc]     = colmax[ni][0];
            s_colmax[wid][cc + 1] = colmax[ni][1];
        }
    }
    __syncthreads();

    float val = 0.f;
    if (tid < 80) {
        float cm = NINF;
#pragma unroll
        for (int w = 0; w < 8; w++) cm = fmaxf(cm, s_colmax[w][tid]);
        val = (tid < len) ? cm : 0.f;
    }
#pragma unroll
    for (int off = 16; off > 0; off >>= 1)
        val += __shfl_xor_sync(0xffffffffu, val, off);
    if (lane == 0) s_part[wid] = val;
    __syncthreads();

    if (tid == 0) {
        float ts = s_part[0] + s_part[1] + s_part[2] + s_part[3];
        float vs = 0.f;
#pragma unroll
        for (int w = 0; w < 8; w++) vs += s_vsum[w];
        t2v[b * NQ + q] = ts / (float)len;
        v2t[b * NQ + q] = vs / (float)NV;
    }
}

// ===========================================================================
extern "C" void kernel_launch(void* const* d_in, const int* in_sizes, int n_in,
                              void* d_out, int out_size)
{
    const float* visual_cls     = (const float*)d_in[0];
    const float* visual_tokens  = (const float*)d_in[1];
    const float* textual_cls    = (const float*)d_in[2];
    const float* textual_tokens = (const float*)d_in[3];
    const float* Wv_cls = (const float*)d_in[4];
    const float* bv_cls = (const float*)d_in[5];
    const float* Wt_cls = (const float*)d_in[6];
    const float* bt_cls = (const float*)d_in[7];
    const float* Wv_tok = (const float*)d_in[8];
    const float* bv_tok = (const float*)d_in[9];
    const float* Wt_tok = (const float*)d_in[10];
    const float* bt_tok = (const float*)d_in[11];
    const int*   text_length = (const int*)d_in[12];

    float* out = (float*)d_out;
    float* o_vcls = out;
    float* o_tcls = out + NB * NE;
    float* o_t2v  = out + 2 * NB * NE;
    float* o_v2t  = o_t2v + NB * NQ;

    static cudaStream_t s2 = nullptr;
    static cudaEvent_t ev_fork = nullptr, ev_join = nullptr;
    if (s2 == nullptr) {
        cudaStreamCreateWithFlags(&s2, cudaStreamNonBlocking);
        cudaEventCreateWithFlags(&ev_fork, cudaEventDisableTiming);
        cudaEventCreateWithFlags(&ev_join, cudaEventDisableTiming);
    }

    // Fork: independent cls projections on side stream
    cudaEventRecord(ev_fork, 0);
    cudaStreamWaitEvent(s2, ev_fork, 0);
    proj_cls<<<dim3(2, 8, 2), 256, 0, s2>>>(visual_cls, Wv_cls, bv_cls, o_vcls,
                                            textual_cls, Wt_cls, bt_cls, o_tcls);
    cudaEventRecord(ev_join, s2);

    // Main chain
    {
        size_t n8 = CSEG3 / 8;
        int blocks = (int)((n8 + 255) / 256);
        convert_bf16<<<blocks, 256>>>(visual_tokens, textual_tokens, Wv_tok, Wt_tok);
    }

    cudaFuncSetAttribute(proj_mma2, cudaFuncAttributeMaxDynamicSharedMemorySize,
                         2 * PSTAGE);
    proj_mma2<<<dim3(VIS_BX, 4, 2), 256, 2 * PSTAGE>>>(bv_tok, bt_tok);

    l2norm_rows<<<(NB * NV + NQ * NT + 7) / 8, 256>>>();

    cudaFuncSetAttribute(stage2, cudaFuncAttributeMaxDynamicSharedMemorySize, SMEM_DYN);
    stage2<<<dim3(NQ, NB), 256, SMEM_DYN>>>(text_length, o_t2v, o_v2t);

    cudaStreamWaitEvent(0, ev_join, 0);
}